// round 1
// baseline (speedup 1.0000x reference)
#include <cuda_runtime.h>
#include <cstdint>

// ---------------- problem constants ----------------
#define BB 32
#define CC 3
#define HH 512
#define WW 512
#define NX 64
#define NY 64
#define KTOT (CC*HH*WW)          // 786432
#define NBLK1 384                // locnet blocks: 384*256*8 = 786432

// ---------------- device scratch (no allocations allowed) ----------------
__device__ float g_partial[NBLK1 * 160];
__device__ float g_p[BB * 5];
__device__ float g_Fx[BB * NX * WW];       // [b][nx][w], row-normalized
__device__ float g_Fy[BB * NY * HH];       // [b][ny][h], row-normalized * gamma
__device__ float g_Gx[BB * CC * HH * NX];  // [b][c][h][m]

// ---------------- packed f32x2 helpers (Blackwell dual-FMA) ----------------
__device__ __forceinline__ unsigned long long pack2(float lo, float hi) {
    unsigned long long r;
    asm("mov.b64 %0, {%1, %2};" : "=l"(r) : "f"(lo), "f"(hi));
    return r;
}
__device__ __forceinline__ unsigned long long fma2(unsigned long long a,
                                                   unsigned long long b,
                                                   unsigned long long c) {
    unsigned long long d;
    asm("fma.rn.f32x2 %0, %1, %2, %3;" : "=l"(d) : "l"(a), "l"(b), "l"(c));
    return d;
}
__device__ __forceinline__ float2 unpack2(unsigned long long v) {
    float2 f;
    asm("mov.b64 {%0, %1}, %2;" : "=f"(f.x), "=f"(f.y) : "l"(v));
    return f;
}

// ============================================================================
// K1: locnet partial sums. Block g covers k in [g*2048, (g+1)*2048).
// W_loc chunk loaded once into registers, reused across all 32 batches.
// ============================================================================
__global__ __launch_bounds__(256) void k_locnet(const float* __restrict__ X,
                                                const float* __restrict__ Wl) {
    const int tid = threadIdx.x;
    const int base = blockIdx.x * 2048;

    float w[8][5];
#pragma unroll
    for (int i = 0; i < 8; i++) {
        const int kk = base + i * 256 + tid;
#pragma unroll
        for (int j = 0; j < 5; j++) w[i][j] = Wl[kk * 5 + j];
    }

    __shared__ float ps[160];
    if (tid < 160) ps[tid] = 0.0f;
    __syncthreads();

    for (int b = 0; b < BB; b++) {
        float acc[5] = {0.f, 0.f, 0.f, 0.f, 0.f};
        const float* Xb = X + (size_t)b * KTOT + base;
#pragma unroll
        for (int i = 0; i < 8; i++) {
            const float x = Xb[i * 256 + tid];
#pragma unroll
            for (int j = 0; j < 5; j++) acc[j] = fmaf(x, w[i][j], acc[j]);
        }
#pragma unroll
        for (int j = 0; j < 5; j++) {
            float v = acc[j];
#pragma unroll
            for (int off = 16; off > 0; off >>= 1)
                v += __shfl_down_sync(0xffffffffu, v, off);
            if ((tid & 31) == 0) atomicAdd(&ps[b * 5 + j], v);
        }
    }
    __syncthreads();
    if (tid < 160) g_partial[blockIdx.x * 160 + tid] = ps[tid];
}

// K1b: deterministic final reduce + bias
__global__ void k_reduce_p(const float* __restrict__ b_loc) {
    const int t = threadIdx.x;  // 160
    float s = 0.0f;
#pragma unroll 8
    for (int g = 0; g < NBLK1; g++) s += g_partial[g * 160 + t];
    g_p[t] = s + b_loc[t % 5];
}

// ============================================================================
// K2: filter banks. grid (64, 2, 32), 128 threads per (b, axis, n) row of 512.
// gamma is folded into Fy.
// ============================================================================
__global__ __launch_bounds__(128) void k_filters() {
    const int n = blockIdx.x;
    const int axis = blockIdx.y;  // 0: Fx (over W), 1: Fy (over H)
    const int b = blockIdx.z;
    const int tid = threadIdx.x;

    const float* pb = g_p + b * 5;
    const float p0 = pb[0], p1 = pb[1], p2 = pb[2], p3 = pb[3], p4 = pb[4];
    const float sigma2 = expf(p2);
    const float delta = expf(p3) * (511.0f / 63.0f);
    const float gctr = (axis == 0) ? 32.0f * (p0 + 1.0f) : 32.0f * (p1 + 1.0f);
    const float m = gctr + delta * ((float)n - 32.5f);
    const float inv2s = 1.0f / (2.0f * sigma2);

    float vals[4];
    float lsum = 0.0f;
#pragma unroll
    for (int i = 0; i < 4; i++) {
        const float a = (float)(tid + i * 128);
        const float d = a - m;
        const float e = expf(-d * d * inv2s);
        vals[i] = e;
        lsum += e;
    }
    __shared__ float sw[4];
#pragma unroll
    for (int off = 16; off > 0; off >>= 1)
        lsum += __shfl_down_sync(0xffffffffu, lsum, off);
    if ((tid & 31) == 0) sw[tid >> 5] = lsum;
    __syncthreads();
    const float tot = sw[0] + sw[1] + sw[2] + sw[3];
    float scale = 1.0f / (tot + 1e-4f);
    if (axis == 1) scale *= expf(p4);  // fold gamma into Fy

    float* dst = (axis == 0 ? g_Fx : g_Fy) + ((size_t)b * 64 + n) * 512;
#pragma unroll
    for (int i = 0; i < 4; i++) dst[tid + i * 128] = vals[i] * scale;
}

// ============================================================================
// K3: Gx[b,c,h,m] = sum_w X[b,c,h,w] * Fx[b,m,w]
// Block tile 128h x 64m, 128 threads, 8x8 register tiles, packed f32x2 FMA.
// grid (4 htiles, 3 c, 32 b)
// ============================================================================
__global__ __launch_bounds__(128) void k_gemm1(const float* __restrict__ X) {
    __shared__ float xs[32][129];   // [w][h]
    __shared__ float fxs[32][65];   // [w][m]

    const int b = blockIdx.z, c = blockIdx.y;
    const int h0 = blockIdx.x * 128;
    const float* Xbc = X + (((size_t)b * CC + c) * HH + h0) * WW;
    const float* Fxb = g_Fx + (size_t)b * 64 * 512;

    const int tid = threadIdx.x;
    const int tx = tid & 7;      // m-group (8 groups of 8)
    const int ty = tid >> 3;     // h-group (16 groups of 8)
    const int lw = (tid & 7) * 4;
    const int lr = tid >> 3;

    unsigned long long acc2[8][4];
#pragma unroll
    for (int i = 0; i < 8; i++)
#pragma unroll
        for (int q = 0; q < 4; q++) acc2[i][q] = 0ull;

    for (int wc = 0; wc < 512; wc += 32) {
        // load X tile (128h x 32w), transposed into xs[w][h]
#pragma unroll
        for (int it = 0; it < 8; it++) {
            const int h = lr + it * 16;
            const float4 v = *(const float4*)&Xbc[h * 512 + wc + lw];
            xs[lw + 0][h] = v.x; xs[lw + 1][h] = v.y;
            xs[lw + 2][h] = v.z; xs[lw + 3][h] = v.w;
        }
        // load Fx tile (64m x 32w), transposed into fxs[w][m]
#pragma unroll
        for (int it = 0; it < 4; it++) {
            const int mm = lr + it * 16;
            const float4 v = *(const float4*)&Fxb[mm * 512 + wc + lw];
            fxs[lw + 0][mm] = v.x; fxs[lw + 1][mm] = v.y;
            fxs[lw + 2][mm] = v.z; fxs[lw + 3][mm] = v.w;
        }
        __syncthreads();

#pragma unroll 8
        for (int w = 0; w < 32; w++) {
            unsigned long long xd[8], fr2[4];
#pragma unroll
            for (int i = 0; i < 8; i++) {
                const float x = xs[w][ty * 8 + i];
                xd[i] = pack2(x, x);
            }
#pragma unroll
            for (int q = 0; q < 4; q++)
                fr2[q] = pack2(fxs[w][tx * 8 + 2 * q], fxs[w][tx * 8 + 2 * q + 1]);
#pragma unroll
            for (int i = 0; i < 8; i++)
#pragma unroll
                for (int q = 0; q < 4; q++)
                    acc2[i][q] = fma2(xd[i], fr2[q], acc2[i][q]);
        }
        __syncthreads();
    }

    float* G = g_Gx + (((size_t)b * CC + c) * HH + h0) * 64;
#pragma unroll
    for (int i = 0; i < 8; i++) {
        const int h = ty * 8 + i;
        float2 a0 = unpack2(acc2[i][0]), a1 = unpack2(acc2[i][1]);
        float2 a2 = unpack2(acc2[i][2]), a3 = unpack2(acc2[i][3]);
        *(float4*)&G[h * 64 + tx * 8 + 0] = make_float4(a0.x, a0.y, a1.x, a1.y);
        *(float4*)&G[h * 64 + tx * 8 + 4] = make_float4(a2.x, a2.y, a3.x, a3.y);
    }
}

// ============================================================================
// K4: out[b,c,n,m] = sum_h Fy'[b,n,h] * Gx[b,c,h,m]   (gamma already in Fy')
// Block per (c, b): 64x64 output, 256 threads, 4x4 tiles, f32x2 FMA.
// ============================================================================
__global__ __launch_bounds__(256) void k_gemm2(float* __restrict__ out) {
    __shared__ float fys[32][65];   // [h][n]
    __shared__ float gxs[32][68];   // [h][m]

    const int c = blockIdx.x, b = blockIdx.y;
    const float* G = g_Gx + ((size_t)b * CC + c) * HH * 64;
    const float* Fyb = g_Fy + (size_t)b * 64 * 512;

    const int tid = threadIdx.x;
    const int tm = tid & 15;    // m-group (16 x 4)
    const int tn = tid >> 4;    // n-group (16 x 4)

    unsigned long long acc2[4][2];
#pragma unroll
    for (int i = 0; i < 4; i++) { acc2[i][0] = 0ull; acc2[i][1] = 0ull; }

    for (int hc = 0; hc < 512; hc += 32) {
        {   // Fy tile: 64n x 32h -> fys[h][n]
            const int lw = (tid & 7) * 4;
            const int r = tid >> 3;  // 0..31
#pragma unroll
            for (int it = 0; it < 2; it++) {
                const int n = r + it * 32;
                const float4 v = *(const float4*)&Fyb[n * 512 + hc + lw];
                fys[lw + 0][n] = v.x; fys[lw + 1][n] = v.y;
                fys[lw + 2][n] = v.z; fys[lw + 3][n] = v.w;
            }
        }
        {   // Gx tile: 32h x 64m -> gxs[h][m] (already row-major in m)
            const int lm = (tid & 15) * 4;
            const int hh = tid >> 4;  // 0..15
#pragma unroll
            for (int it = 0; it < 2; it++) {
                const int h = hh + it * 16;
                const float4 v = *(const float4*)&G[(hc + h) * 64 + lm];
                *(float4*)&gxs[h][lm] = v;
            }
        }
        __syncthreads();

#pragma unroll 8
        for (int h = 0; h < 32; h++) {
            unsigned long long fd[4], gm2[2];
#pragma unroll
            for (int i = 0; i < 4; i++) {
                const float f = fys[h][tn * 4 + i];
                fd[i] = pack2(f, f);
            }
            gm2[0] = pack2(gxs[h][tm * 4 + 0], gxs[h][tm * 4 + 1]);
            gm2[1] = pack2(gxs[h][tm * 4 + 2], gxs[h][tm * 4 + 3]);
#pragma unroll
            for (int i = 0; i < 4; i++) {
                acc2[i][0] = fma2(fd[i], gm2[0], acc2[i][0]);
                acc2[i][1] = fma2(fd[i], gm2[1], acc2[i][1]);
            }
        }
        __syncthreads();
    }

    float* O = out + ((size_t)b * CC + c) * 64 * 64;
#pragma unroll
    for (int i = 0; i < 4; i++) {
        const int n = tn * 4 + i;
        const float2 a0 = unpack2(acc2[i][0]);
        const float2 a1 = unpack2(acc2[i][1]);
        *(float4*)&O[n * 64 + tm * 4] = make_float4(a0.x, a0.y, a1.x, a1.y);
    }
}

// ============================================================================
extern "C" void kernel_launch(void* const* d_in, const int* in_sizes, int n_in,
                              void* d_out, int out_size) {
    (void)in_sizes; (void)n_in; (void)out_size;
    const float* X    = (const float*)d_in[0];
    const float* Wl   = (const float*)d_in[1];
    const float* bloc = (const float*)d_in[2];
    float* out = (float*)d_out;

    k_locnet<<<NBLK1, 256>>>(X, Wl);
    k_reduce_p<<<1, 160>>>(bloc);
    k_filters<<<dim3(64, 2, 32), 128>>>();
    k_gemm1<<<dim3(4, 3, 32), 128>>>(X);
    k_gemm2<<<dim3(3, 32), 256>>>(out);
}